// round 7
// baseline (speedup 1.0000x reference)
#include <cuda_runtime.h>

typedef unsigned long long ull;

// out = (w1+w2)*s + (w3-w2)*G3(s) + (w4-w3)*G5(s) - w4*G7(s)
// Smem-free warp-streaming: each warp owns a 128-col x 64-row strip, streams rows.
// Horizontal taps via lane shuffles (FFMA-imm), vertical via transposed-FIR f32x2 ring.

#define IMG 512
#define CHUNK 64
#define STEPS (CHUNK + 6)    // 70
#define NTH 128
#define WPB (NTH / 32)

#define K3_0 0.5220116f
#define K3_1 0.2389942f
#define K5_0 0.3695467f
#define K5_1 0.2444604f
#define K5_2 0.0707663f
#define K7_0 0.2880262f
#define K7_1 0.2231734f
#define K7_2 0.1038183f
#define K7_3 0.0289952f

__device__ __forceinline__ ull pk2(float lo, float hi) {
    ull r; asm("mov.b64 %0, {%1, %2};" : "=l"(r) : "f"(lo), "f"(hi)); return r;
}
__device__ __forceinline__ ull mul2(ull a, ull b) {
    ull r; asm("mul.rn.f32x2 %0, %1, %2;" : "=l"(r) : "l"(a), "l"(b)); return r;
}
__device__ __forceinline__ ull fma2(ull a, ull b, ull c) {
    ull r; asm("fma.rn.f32x2 %0, %1, %2, %3;" : "=l"(r) : "l"(a), "l"(b), "l"(c)); return r;
}

__global__ void __launch_bounds__(NTH, 6)
mgdf_kernel(const float* __restrict__ s,
            const float* __restrict__ w1p, const float* __restrict__ w2p,
            const float* __restrict__ w3p, const float* __restrict__ w4p,
            float* __restrict__ out)
{
    const int lane = threadIdx.x & 31;
    const int wid  = threadIdx.x >> 5;
    const int g = blockIdx.x * WPB + wid;     // global warp id, 0..6143
    const int img   = g >> 5;                 // 32 warps per image
    const int strip = g & 3;                  // 4 col-strips of 128
    const int chunk = (g >> 2) & 7;           // 8 row-chunks of 64

    const size_t ibase = (size_t)img * (IMG * IMG);
    const int col = strip * 128 + lane * 4;
    const int gy0 = chunk * CHUNK - 3;

    const float* rc = s + ibase + (size_t)gy0 * IMG + col;   // row cursor (deref'd only when valid)
    float* oc = out + ibase + (size_t)(chunk * CHUNK) * IMG + col;

    // Runtime weights folded into vertical coefficients
    const float W1 = *w1p, W2 = *w2p, W3 = *w3p, W4 = *w4p;
    const float cA = W1 + W2, cB = W3 - W2, cC = W4 - W3, cD = -W4;
    const ull cAp = pk2(cA, cA);
    const ull a30 = pk2(cB * K3_0, cB * K3_0);
    const ull a31 = pk2(cB * K3_1, cB * K3_1);
    const ull a50 = pk2(cC * K5_0, cC * K5_0);
    const ull a51 = pk2(cC * K5_1, cC * K5_1);
    const ull a52 = pk2(cC * K5_2, cC * K5_2);
    const ull a70 = pk2(cD * K7_0, cD * K7_0);
    const ull a71 = pk2(cD * K7_1, cD * K7_1);
    const ull a72 = pk2(cD * K7_2, cD * K7_2);
    const ull a73 = pk2(cD * K7_3, cD * K7_3);

    const bool needL = (lane == 0)  && (strip > 0);
    const bool needR = (lane == 31) && (strip < 3);

    ull acc[7][2];
    int gy = gy0;

    for (int i = 0; i < STEPS / 7; i++) {
        #pragma unroll
        for (int j = 0; j < 7; j++) {
            const int k = i * 7 + j;

            // ---- load row (zero-padded at image top/bottom) ----
            const bool valid = ((unsigned)gy < (unsigned)IMG);
            float4 B = make_float4(0.f, 0.f, 0.f, 0.f);
            float el1 = 0.f, el2 = 0.f, el3 = 0.f;
            float er1 = 0.f, er2 = 0.f, er3 = 0.f;
            if (valid) {
                B = *reinterpret_cast<const float4*>(rc);
                if (needL) {
                    float4 E = *reinterpret_cast<const float4*>(rc - 4);
                    el1 = E.y; el2 = E.z; el3 = E.w;      // cols col-3..col-1
                }
                if (needR) {
                    float4 E = *reinterpret_cast<const float4*>(rc + 4);
                    er1 = E.x; er2 = E.y; er3 = E.z;      // cols col+4..col+6
                }
            }

            // ---- halo taps from neighbor lanes ----
            float x1 = __shfl_up_sync(0xFFFFFFFFu, B.y, 1);
            float x2 = __shfl_up_sync(0xFFFFFFFFu, B.z, 1);
            float x3 = __shfl_up_sync(0xFFFFFFFFu, B.w, 1);
            float x8 = __shfl_down_sync(0xFFFFFFFFu, B.x, 1);
            float x9 = __shfl_down_sync(0xFFFFFFFFu, B.y, 1);
            float x10 = __shfl_down_sync(0xFFFFFFFFu, B.z, 1);
            if (lane == 0)  { x1 = el1; x2 = el2; x3 = el3; }
            if (lane == 31) { x8 = er1; x9 = er2; x10 = er3; }
            const float x4 = B.x, x5 = B.y, x6 = B.z, x7 = B.w;

            // ---- horizontal pass: 4 cols, scalar FFMA-imm ----
            float h3v[4], h5v[4], h7v[4];
            {
                float p1, p2, p3;
                p1 = x3 + x5;  p2 = x2 + x6;  p3 = x1 + x7;
                h3v[0] = K3_0 * x4 + K3_1 * p1;
                h5v[0] = K5_0 * x4 + K5_1 * p1 + K5_2 * p2;
                h7v[0] = K7_0 * x4 + K7_1 * p1 + K7_2 * p2 + K7_3 * p3;
                p1 = x4 + x6;  p2 = x3 + x7;  p3 = x2 + x8;
                h3v[1] = K3_0 * x5 + K3_1 * p1;
                h5v[1] = K5_0 * x5 + K5_1 * p1 + K5_2 * p2;
                h7v[1] = K7_0 * x5 + K7_1 * p1 + K7_2 * p2 + K7_3 * p3;
                p1 = x5 + x7;  p2 = x4 + x8;  p3 = x3 + x9;
                h3v[2] = K3_0 * x6 + K3_1 * p1;
                h5v[2] = K5_0 * x6 + K5_1 * p1 + K5_2 * p2;
                h7v[2] = K7_0 * x6 + K7_1 * p1 + K7_2 * p2 + K7_3 * p3;
                p1 = x6 + x8;  p2 = x5 + x9;  p3 = x4 + x10;
                h3v[3] = K3_0 * x7 + K3_1 * p1;
                h5v[3] = K5_0 * x7 + K5_1 * p1 + K5_2 * p2;
                h7v[3] = K7_0 * x7 + K7_1 * p1 + K7_2 * p2 + K7_3 * p3;
            }
            ull t3a = pk2(h3v[0], h3v[1]), t3b = pk2(h3v[2], h3v[3]);
            ull t5a = pk2(h5v[0], h5v[1]), t5b = pk2(h5v[2], h5v[3]);
            ull t7a = pk2(h7v[0], h7v[1]), t7b = pk2(h7v[2], h7v[3]);
            ull rwa = pk2(x4, x5),          rwb = pk2(x6, x7);

            // ---- transposed-FIR ring (slots compile-time via j) ----
            // Unguarded updates: slots touched for out-of-range outputs are
            // always re-initialized by their d0 mul2 before any store.
            {   // d=0 init, slot j
                acc[j][0] = mul2(a73, t7a);
                acc[j][1] = mul2(a73, t7b);
            }
            {   // d=1, slot (j+6)%7
                const int sl = (j + 6) % 7;
                ull u = acc[sl][0], v = acc[sl][1];
                u = fma2(a72, t7a, u);  v = fma2(a72, t7b, v);
                u = fma2(a52, t5a, u);  v = fma2(a52, t5b, v);
                acc[sl][0] = u; acc[sl][1] = v;
            }
            {   // d=2, slot (j+5)%7
                const int sl = (j + 5) % 7;
                ull u = acc[sl][0], v = acc[sl][1];
                u = fma2(a71, t7a, u);  v = fma2(a71, t7b, v);
                u = fma2(a51, t5a, u);  v = fma2(a51, t5b, v);
                u = fma2(a31, t3a, u);  v = fma2(a31, t3b, v);
                acc[sl][0] = u; acc[sl][1] = v;
            }
            {   // d=3 (center), slot (j+4)%7
                const int sl = (j + 4) % 7;
                ull u = acc[sl][0], v = acc[sl][1];
                u = fma2(a70, t7a, u);  v = fma2(a70, t7b, v);
                u = fma2(a50, t5a, u);  v = fma2(a50, t5b, v);
                u = fma2(a30, t3a, u);  v = fma2(a30, t3b, v);
                u = fma2(cAp, rwa, u);  v = fma2(cAp, rwb, v);
                acc[sl][0] = u; acc[sl][1] = v;
            }
            {   // d=4, slot (j+3)%7
                const int sl = (j + 3) % 7;
                ull u = acc[sl][0], v = acc[sl][1];
                u = fma2(a71, t7a, u);  v = fma2(a71, t7b, v);
                u = fma2(a51, t5a, u);  v = fma2(a51, t5b, v);
                u = fma2(a31, t3a, u);  v = fma2(a31, t3b, v);
                acc[sl][0] = u; acc[sl][1] = v;
            }
            {   // d=5, slot (j+2)%7
                const int sl = (j + 2) % 7;
                ull u = acc[sl][0], v = acc[sl][1];
                u = fma2(a72, t7a, u);  v = fma2(a72, t7b, v);
                u = fma2(a52, t5a, u);  v = fma2(a52, t5b, v);
                acc[sl][0] = u; acc[sl][1] = v;
            }
            if (k >= 6) {   // d=6: finish + STG.128, consecutive rows
                const int sl = (j + 1) % 7;
                ulonglong2 o;
                o.x = fma2(a73, t7a, acc[sl][0]);
                o.y = fma2(a73, t7b, acc[sl][1]);
                *reinterpret_cast<ulonglong2*>(oc) = o;
                oc += IMG;
            }

            gy++;
            rc += IMG;
        }
    }
}

extern "C" void kernel_launch(void* const* d_in, const int* in_sizes, int n_in,
                              void* d_out, int out_size)
{
    const float* s  = (const float*)d_in[0];
    const float* w1 = (const float*)d_in[1];
    const float* w2 = (const float*)d_in[2];
    const float* w3 = (const float*)d_in[3];
    const float* w4 = (const float*)d_in[4];
    float* out = (float*)d_out;

    const int n_img = in_sizes[0] / (IMG * IMG);        // 192
    const int n_warps = n_img * 32;                     // 4 strips x 8 chunks per image
    dim3 grid(n_warps / WPB, 1, 1);                     // 1536 blocks
    mgdf_kernel<<<grid, NTH>>>(s, w1, w2, w3, w4, out);
}